// round 2
// baseline (speedup 1.0000x reference)
#include <cuda_runtime.h>
#include <cuda_bf16.h>
#include <math.h>

// Problem constants
#define BATCH   2
#define SEQ     2048
#define HID     1024
#define VOCAB_N 32000
#define ROWS    (BATCH * SEQ)   // 4096

// Scratch (static device allocations are the permitted scratch mechanism)
__device__ float g_h[ROWS * HID];                 // 16.8 MB
__device__ float g_q[ROWS * HID];
__device__ float g_k[ROWS * HID];
__device__ float g_v[ROWS * HID];
__device__ float g_attn[(size_t)BATCH * SEQ * SEQ];  // 33.6 MB (scores in-place softmax)
__device__ float g_z[ROWS * HID];

// ---------------------------------------------------------------------------
// Embedding: h[row,:] = emb[x[row],:] + pos_emb[row % SEQ,:]
// ---------------------------------------------------------------------------
__global__ void embed_kernel(const int* __restrict__ x,
                             const float* __restrict__ emb,
                             const float* __restrict__ pos) {
    int row = blockIdx.x;            // 0..4095
    int s = row & (SEQ - 1);
    int tok = x[row];
    const float4* e  = (const float4*)(emb + (size_t)tok * HID);
    const float4* pe = (const float4*)(pos + (size_t)s * HID);
    float4* o = (float4*)(g_h + (size_t)row * HID);
    int t = threadIdx.x;             // 0..255, 256*4 = 1024 floats
    float4 a = e[t], b = pe[t];
    o[t] = make_float4(a.x + b.x, a.y + b.y, a.z + b.z, a.w + b.w);
}

// ---------------------------------------------------------------------------
// Generic NN SGEMM: C = A[M,K] * B[K,N] (+ bias[N]) (+ residual)
// BM=BN=128, BK=16, 256 threads, 8x8 per thread. All dims multiples of tile.
// causal_kmax != 0 => K-loop limited to min(K, m0+BM)  (attn rows are causal)
// Batch via blockIdx.z with element strides.
// ---------------------------------------------------------------------------
#define BM 128
#define BN 128
#define BK 16

__global__ void __launch_bounds__(256)
sgemm_nn(const float* __restrict__ A, const float* __restrict__ B,
         float* __restrict__ C,
         int M, int N, int K, int lda, int ldb, int ldc,
         const float* __restrict__ bias,
         const float* __restrict__ residual,
         int causal_kmax,
         size_t sA, size_t sB, size_t sC, size_t sR) {
    __shared__ float As[BK][BM];
    __shared__ float Bs[BK][BN];

    int zb = blockIdx.z;
    A += sA * zb; B += sB * zb; C += sC * zb;
    if (residual) residual += sR * zb;

    int tid = threadIdx.x;
    int m0 = blockIdx.y * BM;
    int n0 = blockIdx.x * BN;
    int kend = causal_kmax ? min(K, m0 + BM) : K;

    float acc[8][8];
    #pragma unroll
    for (int i = 0; i < 8; i++)
        #pragma unroll
        for (int j = 0; j < 8; j++) acc[i][j] = 0.0f;

    const int rm = (tid >> 4) << 3;   // 0,8,..,120
    const int cn = (tid & 15) << 3;

    for (int k0 = 0; k0 < kend; k0 += BK) {
        // Load A tile (BMxBK), store transposed
        #pragma unroll
        for (int t = 0; t < 2; t++) {
            int i = tid + t * 256;
            int r = i >> 2, c4 = (i & 3) << 2;
            float4 av = *(const float4*)&A[(size_t)(m0 + r) * lda + k0 + c4];
            As[c4 + 0][r] = av.x; As[c4 + 1][r] = av.y;
            As[c4 + 2][r] = av.z; As[c4 + 3][r] = av.w;
        }
        // Load B tile (BKxBN) direct
        #pragma unroll
        for (int t = 0; t < 2; t++) {
            int i = tid + t * 256;
            int r = i >> 5, c = (i & 31) << 2;
            *(float4*)&Bs[r][c] = *(const float4*)&B[(size_t)(k0 + r) * ldb + n0 + c];
        }
        __syncthreads();
        #pragma unroll
        for (int kk = 0; kk < BK; kk++) {
            float a[8], b[8];
            *(float4*)&a[0] = *(float4*)&As[kk][rm];
            *(float4*)&a[4] = *(float4*)&As[kk][rm + 4];
            *(float4*)&b[0] = *(float4*)&Bs[kk][cn];
            *(float4*)&b[4] = *(float4*)&Bs[kk][cn + 4];
            #pragma unroll
            for (int i = 0; i < 8; i++)
                #pragma unroll
                for (int j = 0; j < 8; j++)
                    acc[i][j] += a[i] * b[j];
        }
        __syncthreads();
    }

    // Epilogue
    int gm = m0 + rm, gn = n0 + cn;
    #pragma unroll
    for (int i = 0; i < 8; i++) {
        size_t base = (size_t)(gm + i) * ldc + gn;
        #pragma unroll
        for (int j = 0; j < 8; j += 4) {
            float4 vv = make_float4(acc[i][j], acc[i][j+1], acc[i][j+2], acc[i][j+3]);
            if (bias) {
                float4 bb = *(const float4*)&bias[gn + j];
                vv.x += bb.x; vv.y += bb.y; vv.z += bb.z; vv.w += bb.w;
            }
            if (residual) {
                float4 rr = *(const float4*)&residual[base + j];
                vv.x += rr.x; vv.y += rr.y; vv.z += rr.z; vv.w += rr.w;
            }
            *(float4*)&C[base + j] = vv;
        }
    }
}

// ---------------------------------------------------------------------------
// NT SGEMM for causal scores: C[s,t] = scale * dot(A[s,:], B[t,:])
// Skips blocks strictly above the diagonal. Batched via blockIdx.z.
// ---------------------------------------------------------------------------
__global__ void __launch_bounds__(256)
sgemm_nt_causal(const float* __restrict__ A, const float* __restrict__ B,
                float* __restrict__ C, int K, int lda, int ldb, int ldc,
                float scale, size_t sA, size_t sB, size_t sC) {
    if (blockIdx.x > blockIdx.y) return;   // block fully above diagonal
    __shared__ float As[BK][BM];
    __shared__ float Bs[BK][BN];

    int zb = blockIdx.z;
    A += sA * zb; B += sB * zb; C += sC * zb;

    int tid = threadIdx.x;
    int m0 = blockIdx.y * BM;
    int n0 = blockIdx.x * BN;

    float acc[8][8];
    #pragma unroll
    for (int i = 0; i < 8; i++)
        #pragma unroll
        for (int j = 0; j < 8; j++) acc[i][j] = 0.0f;

    const int rm = (tid >> 4) << 3;
    const int cn = (tid & 15) << 3;

    for (int k0 = 0; k0 < K; k0 += BK) {
        #pragma unroll
        for (int t = 0; t < 2; t++) {
            int i = tid + t * 256;
            int r = i >> 2, c4 = (i & 3) << 2;
            float4 av = *(const float4*)&A[(size_t)(m0 + r) * lda + k0 + c4];
            As[c4 + 0][r] = av.x; As[c4 + 1][r] = av.y;
            As[c4 + 2][r] = av.z; As[c4 + 3][r] = av.w;
        }
        #pragma unroll
        for (int t = 0; t < 2; t++) {
            int i = tid + t * 256;
            int r = i >> 2, c4 = (i & 3) << 2;
            float4 bv = *(const float4*)&B[(size_t)(n0 + r) * ldb + k0 + c4];
            Bs[c4 + 0][r] = bv.x; Bs[c4 + 1][r] = bv.y;
            Bs[c4 + 2][r] = bv.z; Bs[c4 + 3][r] = bv.w;
        }
        __syncthreads();
        #pragma unroll
        for (int kk = 0; kk < BK; kk++) {
            float a[8], b[8];
            *(float4*)&a[0] = *(float4*)&As[kk][rm];
            *(float4*)&a[4] = *(float4*)&As[kk][rm + 4];
            *(float4*)&b[0] = *(float4*)&Bs[kk][cn];
            *(float4*)&b[4] = *(float4*)&Bs[kk][cn + 4];
            #pragma unroll
            for (int i = 0; i < 8; i++)
                #pragma unroll
                for (int j = 0; j < 8; j++)
                    acc[i][j] += a[i] * b[j];
        }
        __syncthreads();
    }

    int gm = m0 + rm, gn = n0 + cn;
    #pragma unroll
    for (int i = 0; i < 8; i++) {
        size_t base = (size_t)(gm + i) * ldc + gn;
        #pragma unroll
        for (int j = 0; j < 8; j += 4) {
            float4 vv = make_float4(acc[i][j] * scale, acc[i][j+1] * scale,
                                    acc[i][j+2] * scale, acc[i][j+3] * scale);
            *(float4*)&C[base + j] = vv;
        }
    }
}

// ---------------------------------------------------------------------------
// In-place causal softmax over rows of g_attn. One block per row.
// Row (b,s): softmax over t in [0, s], zeros for t > s.
// ---------------------------------------------------------------------------
__global__ void softmax_causal_kernel() {
    int row = blockIdx.x;                 // 0..4095 = b*SEQ + s
    int s = row & (SEQ - 1);
    float* p = g_attn + (size_t)row * SEQ;
    int L = s + 1;
    __shared__ float red[256];
    int tid = threadIdx.x;

    float m = -1e30f;
    for (int t = tid; t < L; t += 256) m = fmaxf(m, p[t]);
    red[tid] = m; __syncthreads();
    #pragma unroll
    for (int o = 128; o > 0; o >>= 1) {
        if (tid < o) red[tid] = fmaxf(red[tid], red[tid + o]);
        __syncthreads();
    }
    m = red[0]; __syncthreads();

    float sum = 0.0f;
    for (int t = tid; t < L; t += 256) {
        float e = __expf(p[t] - m);
        p[t] = e;
        sum += e;
    }
    red[tid] = sum; __syncthreads();
    #pragma unroll
    for (int o = 128; o > 0; o >>= 1) {
        if (tid < o) red[tid] += red[tid + o];
        __syncthreads();
    }
    float inv = 1.0f / red[0];

    for (int t = tid; t < L; t += 256) p[t] *= inv;
    for (int t = L + tid; t < SEQ; t += 256) p[t] = 0.0f;
}

// ---------------------------------------------------------------------------
extern "C" void kernel_launch(void* const* d_in, const int* in_sizes, int n_in,
                              void* d_out, int out_size) {
    const int*   x    = (const int*)  d_in[0];
    const float* emb  = (const float*)d_in[1];
    const float* pos  = (const float*)d_in[2];
    const float* Wk   = (const float*)d_in[3];
    const float* Wq   = (const float*)d_in[4];
    const float* Wv   = (const float*)d_in[5];
    const float* Wo   = (const float*)d_in[6];
    const float* bo   = (const float*)d_in[7];
    float* out = (float*)d_out;

    // Resolve scratch symbol addresses once (first call is the uncaptured
    // correctness run); captured replays see only cached pointers.
    static float *h = nullptr, *q, *k, *v, *attn, *z;
    if (!h) {
        cudaGetSymbolAddress((void**)&h,    g_h);
        cudaGetSymbolAddress((void**)&q,    g_q);
        cudaGetSymbolAddress((void**)&k,    g_k);
        cudaGetSymbolAddress((void**)&v,    g_v);
        cudaGetSymbolAddress((void**)&attn, g_attn);
        cudaGetSymbolAddress((void**)&z,    g_z);
    }

    // 1. Embedding
    embed_kernel<<<ROWS, 256>>>(x, emb, pos);

    // 2. Q, K, V projections: [4096,1024] x [1024,1024]
    {
        dim3 grid(HID / BN, ROWS / BM, 1);
        sgemm_nn<<<grid, 256>>>(h, Wq, q, ROWS, HID, HID, HID, HID, HID,
                                nullptr, nullptr, 0, 0, 0, 0, 0);
        sgemm_nn<<<grid, 256>>>(h, Wk, k, ROWS, HID, HID, HID, HID, HID,
                                nullptr, nullptr, 0, 0, 0, 0, 0);
        sgemm_nn<<<grid, 256>>>(h, Wv, v, ROWS, HID, HID, HID, HID, HID,
                                nullptr, nullptr, 0, 0, 0, 0, 0);
    }

    // 3. scores = q @ k^T / sqrt(H), causal blocks only
    {
        dim3 grid(SEQ / BN, SEQ / BM, BATCH);
        float scale = 1.0f / sqrtf((float)HID);
        sgemm_nt_causal<<<grid, 256>>>(q, k, attn, HID, HID, HID, SEQ, scale,
                                       (size_t)SEQ * HID, (size_t)SEQ * HID,
                                       (size_t)SEQ * SEQ);
    }

    // 4. causal softmax in place
    softmax_causal_kernel<<<ROWS, 256>>>();

    // 5. z = attn @ v + h   (K limited by causality per row-block)
    {
        dim3 grid(HID / BN, SEQ / BM, BATCH);
        sgemm_nn<<<grid, 256>>>(attn, v, z, SEQ, HID, SEQ, SEQ, HID, HID,
                                nullptr, h, 1,
                                (size_t)SEQ * SEQ, (size_t)SEQ * HID,
                                (size_t)SEQ * HID, (size_t)SEQ * HID);
    }

    // 6. out = z @ Wo + bo : [4096,1024] x [1024,32000]
    {
        dim3 grid(VOCAB_N / BN, ROWS / BM, 1);
        sgemm_nn<<<grid, 256>>>(z, Wo, out, ROWS, VOCAB_N, HID, HID, VOCAB_N,
                                VOCAB_N, bo, nullptr, 0, 0, 0, 0, 0);
    }
}

// round 5
// speedup vs baseline: 3.0894x; 3.0894x over previous
#include <cuda_runtime.h>
#include <cuda_bf16.h>
#include <math.h>
#include <stdint.h>

// ---------------------------------------------------------------- constants
#define BATCH   2
#define SEQ     2048
#define HID     1024
#define VOCAB_N 32000
#define ROWS    (BATCH * SEQ)     // 4096

#define BM 128
#define BN 128
#define BK 16
#define BMp 20     // [row][k] pad: bank stride 20 -> conflict-free frag loads
#define BNp 136    // [k][n] pad: 136 % 32 == 8 -> conflict-free frag loads

// ---------------------------------------------------------------- scratch
__device__ float g_h[ROWS * HID];
__device__ float g_qkv[3 * (size_t)ROWS * HID];            // q | k | v
__device__ float g_attn[(size_t)BATCH * SEQ * SEQ];
__device__ float g_z[ROWS * HID];

// ---------------------------------------------------------------- helpers
__device__ __forceinline__ uint32_t tf32r(float x) {
    uint32_t r;
    asm("cvt.rna.tf32.f32 %0, %1;" : "=r"(r) : "f"(x));
    return r;
}
__device__ __forceinline__ void mma8(float* cc, const uint32_t* a,
                                     uint32_t b0, uint32_t b1) {
    asm volatile(
        "mma.sync.aligned.m16n8k8.row.col.f32.tf32.tf32.f32 "
        "{%0,%1,%2,%3}, {%4,%5,%6,%7}, {%8,%9}, {%0,%1,%2,%3};"
        : "+f"(cc[0]), "+f"(cc[1]), "+f"(cc[2]), "+f"(cc[3])
        : "r"(a[0]), "r"(a[1]), "r"(a[2]), "r"(a[3]), "r"(b0), "r"(b1));
}

// ---------------------------------------------------------------- embedding
__global__ void embed_kernel(const int* __restrict__ x,
                             const float* __restrict__ emb,
                             const float* __restrict__ pos) {
    int row = blockIdx.x;
    int s = row & (SEQ - 1);
    int tok = x[row];
    const float4* e  = (const float4*)(emb + (size_t)tok * HID);
    const float4* pe = (const float4*)(pos + (size_t)s * HID);
    float4* o = (float4*)(g_h + (size_t)row * HID);
    int t = threadIdx.x;
    float4 a = e[t], b = pe[t];
    o[t] = make_float4(a.x + b.x, a.y + b.y, a.z + b.z, a.w + b.w);
}

// ---------------------------------------------------------------- tf32 mma GEMM
// C[M,N] = A[M,K] * B  (+bias +residual, *scale)
//   BT=0: B is [K,N] row-major (ldb = row stride)
//   BT=1: B is [N,K] row-major (C = A * B^T)
// causal_skip: skip CTA if block above diagonal (square tiles).
// causal_klimit: K-loop limited to m0+BM.
template <int BT>
__global__ void __launch_bounds__(256, 2)
mma_gemm(const float* __restrict__ A, const float* __restrict__ B,
         float* __restrict__ C, int K, int lda, int ldb, int ldc,
         const float* __restrict__ bias, const float* __restrict__ residual,
         float scale, int causal_skip, int causal_klimit,
         size_t sA, size_t sB, size_t sC, size_t sR) {
    if (causal_skip && blockIdx.x > blockIdx.y) return;

    __shared__ __align__(16) float As[2][BM * BMp];
    __shared__ __align__(16) float Bs[2][BT ? (BN * BMp) : (BK * BNp)];

    const int m0 = blockIdx.y * BM;
    const int n0 = blockIdx.x * BN;
    const int zb = blockIdx.z;
    A += sA * zb; B += sB * zb; C += sC * zb;
    if (residual) residual += sR * zb;

    const int kend = causal_klimit ? min(K, m0 + BM) : K;
    const int KT = kend / BK;

    const int tid  = threadIdx.x;
    const int lane = tid & 31;
    const int c = lane & 3;        // k-quad within fragment
    const int d = lane >> 2;       // row/col group within fragment
    const int wid = tid >> 5;
    const int wm = wid & 3;        // warp m index (0..3)
    const int wn = wid >> 2;       // warp n index (0..1)

    float acc[2][8][4];
    #pragma unroll
    for (int mt = 0; mt < 2; mt++)
        #pragma unroll
        for (int j = 0; j < 8; j++)
            #pragma unroll
            for (int t = 0; t < 4; t++) acc[mt][j][t] = 0.0f;

    float4 pa[2], pb[2];

    // global -> regs
    auto ldg = [&](int k0) {
        #pragma unroll
        for (int i = 0; i < 2; i++) {
            int idx = tid + i * 256;
            int r = idx >> 2, cq = idx & 3;
            pa[i] = *(const float4*)&A[(size_t)(m0 + r) * lda + k0 + cq * 4];
            if (BT) {
                pb[i] = *(const float4*)&B[(size_t)(n0 + r) * ldb + k0 + cq * 4];
            } else {
                int rb = idx >> 5, cb = idx & 31;
                pb[i] = *(const float4*)&B[(size_t)(k0 + rb) * ldb + n0 + cb * 4];
            }
        }
    };
    // regs -> smem (with tf32 rounding)
    auto sts = [&](int bf) {
        #pragma unroll
        for (int i = 0; i < 2; i++) {
            int idx = tid + i * 256;
            int r = idx >> 2, cq = idx & 3;
            float* pA = &As[bf][r * BMp + cq * 4];
            pA[0] = __uint_as_float(tf32r(pa[i].x));
            pA[1] = __uint_as_float(tf32r(pa[i].y));
            pA[2] = __uint_as_float(tf32r(pa[i].z));
            pA[3] = __uint_as_float(tf32r(pa[i].w));
            float* pB;
            if (BT) {
                pB = &Bs[bf][r * BMp + cq * 4];
            } else {
                int rb = idx >> 5, cb = idx & 31;
                pB = &Bs[bf][rb * BNp + cb * 4];
            }
            pB[0] = __uint_as_float(tf32r(pb[i].x));
            pB[1] = __uint_as_float(tf32r(pb[i].y));
            pB[2] = __uint_as_float(tf32r(pb[i].z));
            pB[3] = __uint_as_float(tf32r(pb[i].w));
        }
    };

    ldg(0);
    sts(0);
    __syncthreads();

    for (int kt = 0; kt < KT; kt++) {
        const int cur = kt & 1;
        if (kt + 1 < KT) ldg((kt + 1) * BK);

        #pragma unroll
        for (int s = 0; s < 2; s++) {
            const int kk = s * 8 + c;
            uint32_t a[2][4];
            #pragma unroll
            for (int mt = 0; mt < 2; mt++) {
                int r0 = wm * 32 + mt * 16 + d;
                a[mt][0] = __float_as_uint(As[cur][r0 * BMp + kk]);
                a[mt][1] = __float_as_uint(As[cur][(r0 + 8) * BMp + kk]);
                a[mt][2] = __float_as_uint(As[cur][r0 * BMp + kk + 4]);
                a[mt][3] = __float_as_uint(As[cur][(r0 + 8) * BMp + kk + 4]);
            }
            #pragma unroll
            for (int j = 0; j < 8; j++) {
                uint32_t b0, b1;
                if (BT) {
                    int rn = (wn * 64 + j * 8 + d) * BMp;
                    b0 = __float_as_uint(Bs[cur][rn + kk]);
                    b1 = __float_as_uint(Bs[cur][rn + kk + 4]);
                } else {
                    int nn = wn * 64 + j * 8 + d;
                    b0 = __float_as_uint(Bs[cur][kk * BNp + nn]);
                    b1 = __float_as_uint(Bs[cur][(kk + 4) * BNp + nn]);
                }
                mma8(acc[0][j], a[0], b0, b1);
                mma8(acc[1][j], a[1], b0, b1);
            }
        }

        if (kt + 1 < KT) {
            __syncthreads();        // everyone done reading buffer (kt+1)&1
            sts((kt + 1) & 1);
            __syncthreads();        // publish
        }
    }

    // ---- epilogue
    #pragma unroll
    for (int mt = 0; mt < 2; mt++) {
        int row0 = m0 + wm * 32 + mt * 16 + d;
        #pragma unroll
        for (int j = 0; j < 8; j++) {
            int col = n0 + wn * 64 + j * 8 + 2 * c;
            float bx = 0.0f, by = 0.0f;
            if (bias) { bx = bias[col]; by = bias[col + 1]; }
            {
                size_t o0 = (size_t)row0 * ldc + col;
                float2 vv;
                vv.x = acc[mt][j][0] * scale + bx;
                vv.y = acc[mt][j][1] * scale + by;
                if (residual) {
                    vv.x += residual[o0];
                    vv.y += residual[o0 + 1];
                }
                *(float2*)&C[o0] = vv;
            }
            {
                size_t o1 = (size_t)(row0 + 8) * ldc + col;
                float2 vv;
                vv.x = acc[mt][j][2] * scale + bx;
                vv.y = acc[mt][j][3] * scale + by;
                if (residual) {
                    vv.x += residual[o1];
                    vv.y += residual[o1 + 1];
                }
                *(float2*)&C[o1] = vv;
            }
        }
    }
}

// ---------------------------------------------------------------- softmax
__global__ void softmax_causal_kernel() {
    int row = blockIdx.x;
    int s = row & (SEQ - 1);
    float* p = g_attn + (size_t)row * SEQ;
    int L = s + 1;
    __shared__ float red[256];
    int tid = threadIdx.x;

    float m = -1e30f;
    for (int t = tid; t < L; t += 256) m = fmaxf(m, p[t]);
    red[tid] = m; __syncthreads();
    #pragma unroll
    for (int o = 128; o > 0; o >>= 1) {
        if (tid < o) red[tid] = fmaxf(red[tid], red[tid + o]);
        __syncthreads();
    }
    m = red[0]; __syncthreads();

    float sum = 0.0f;
    for (int t = tid; t < L; t += 256) {
        float e = __expf(p[t] - m);
        p[t] = e;
        sum += e;
    }
    red[tid] = sum; __syncthreads();
    #pragma unroll
    for (int o = 128; o > 0; o >>= 1) {
        if (tid < o) red[tid] += red[tid + o];
        __syncthreads();
    }
    float inv = 1.0f / red[0];

    for (int t = tid; t < L; t += 256) p[t] *= inv;
    for (int t = L + tid; t < SEQ; t += 256) p[t] = 0.0f;
}

// ---------------------------------------------------------------- launch
extern "C" void kernel_launch(void* const* d_in, const int* in_sizes, int n_in,
                              void* d_out, int out_size) {
    const int*   x    = (const int*)  d_in[0];
    const float* emb  = (const float*)d_in[1];
    const float* pos  = (const float*)d_in[2];
    const float* Wk   = (const float*)d_in[3];
    const float* Wq   = (const float*)d_in[4];
    const float* Wv   = (const float*)d_in[5];
    const float* Wo   = (const float*)d_in[6];
    const float* bo   = (const float*)d_in[7];
    float* out = (float*)d_out;

    static float *h = nullptr, *qkv, *attn, *z;
    if (!h) {
        cudaGetSymbolAddress((void**)&h,    g_h);
        cudaGetSymbolAddress((void**)&qkv,  g_qkv);
        cudaGetSymbolAddress((void**)&attn, g_attn);
        cudaGetSymbolAddress((void**)&z,    g_z);
    }
    const size_t SH = (size_t)SEQ * HID;
    const size_t RH = (size_t)ROWS * HID;
    const size_t SS = (size_t)SEQ * SEQ;

    // 1. embedding
    embed_kernel<<<ROWS, 256>>>(x, emb, pos);

    // 2. QKV projections: [4096,1024] x [1024,1024]
    {
        dim3 grid(HID / BN, ROWS / BM, 1);
        mma_gemm<0><<<grid, 256>>>(h, Wq, qkv,          HID, HID, HID, HID,
                                   nullptr, nullptr, 1.0f, 0, 0, 0, 0, 0, 0);
        mma_gemm<0><<<grid, 256>>>(h, Wk, qkv + RH,     HID, HID, HID, HID,
                                   nullptr, nullptr, 1.0f, 0, 0, 0, 0, 0, 0);
        mma_gemm<0><<<grid, 256>>>(h, Wv, qkv + 2 * RH, HID, HID, HID, HID,
                                   nullptr, nullptr, 1.0f, 0, 0, 0, 0, 0, 0);
    }

    // 3. scores = q k^T / 32 (causal blocks only);  B^T mode from k [SEQ,HID]
    {
        dim3 grid(SEQ / BN, SEQ / BM, BATCH);
        mma_gemm<1><<<grid, 256>>>(qkv, qkv + RH, attn, HID, HID, HID, SEQ,
                                   nullptr, nullptr, 1.0f / 32.0f, 1, 0,
                                   SH, SH, SS, 0);
    }

    // 4. causal softmax in place
    softmax_causal_kernel<<<ROWS, 256>>>();

    // 5. z = attn @ v + h   (K causally limited per row-block)
    {
        dim3 grid(HID / BN, SEQ / BM, BATCH);
        mma_gemm<0><<<grid, 256>>>(attn, qkv + 2 * RH, z, SEQ, SEQ, HID, HID,
                                   nullptr, h, 1.0f, 0, 1,
                                   SS, SH, SH, SH);
    }

    // 6. out = z @ Wo + bo : [4096,1024] x [1024,32000]
    {
        dim3 grid(VOCAB_N / BN, ROWS / BM, 1);
        mma_gemm<0><<<grid, 256>>>(z, Wo, out, HID, HID, VOCAB_N, VOCAB_N,
                                   bo, nullptr, 1.0f, 0, 0, 0, 0, 0, 0);
    }
}

// round 9
// speedup vs baseline: 3.2812x; 1.0621x over previous
#include <cuda_runtime.h>
#include <cuda_bf16.h>
#include <math.h>
#include <stdint.h>

// ---------------------------------------------------------------- constants
#define BATCH   2
#define SEQ     2048
#define HID     1024
#define VOCAB_N 32000
#define ROWS    (BATCH * SEQ)     // 4096

#define BM 128
#define BN 128
#define BK 16
#define BMp 20     // [row][k] pad: bank stride 20 -> conflict-free frag loads
#define BNp 136    // [k][n] pad: 136 % 32 == 8 -> conflict-free frag loads

// ---------------------------------------------------------------- scratch
__device__ float g_h[ROWS * HID];
__device__ float g_qkv[3 * (size_t)ROWS * HID];            // q | k | v
__device__ float g_attn[(size_t)BATCH * SEQ * SEQ];
__device__ float g_z[ROWS * HID];
__device__ float g_wR[3 * (size_t)HID * HID + (size_t)HID * VOCAB_N]; // rounded weights

// ---------------------------------------------------------------- helpers
__device__ __forceinline__ uint32_t tf32r(float x) {
    uint32_t r;
    asm("cvt.rna.tf32.f32 %0, %1;" : "=r"(r) : "f"(x));
    return r;
}
__device__ __forceinline__ float tf32f(float x) { return __uint_as_float(tf32r(x)); }

__device__ __forceinline__ void mma8(float* cc, const uint32_t* a,
                                     uint32_t b0, uint32_t b1) {
    asm volatile(
        "mma.sync.aligned.m16n8k8.row.col.f32.tf32.tf32.f32 "
        "{%0,%1,%2,%3}, {%4,%5,%6,%7}, {%8,%9}, {%0,%1,%2,%3};"
        : "+f"(cc[0]), "+f"(cc[1]), "+f"(cc[2]), "+f"(cc[3])
        : "r"(a[0]), "r"(a[1]), "r"(a[2]), "r"(a[3]), "r"(b0), "r"(b1));
}

// ---------------------------------------------------------------- embedding (tf32-rounded h)
__global__ void embed_kernel(const int* __restrict__ x,
                             const float* __restrict__ emb,
                             const float* __restrict__ pos) {
    int row = blockIdx.x;
    int s = row & (SEQ - 1);
    int tok = x[row];
    const float4* e  = (const float4*)(emb + (size_t)tok * HID);
    const float4* pe = (const float4*)(pos + (size_t)s * HID);
    float4* o = (float4*)(g_h + (size_t)row * HID);
    int t = threadIdx.x;
    float4 a = e[t], b = pe[t];
    o[t] = make_float4(tf32f(a.x + b.x), tf32f(a.y + b.y),
                       tf32f(a.z + b.z), tf32f(a.w + b.w));
}

// ---------------------------------------------------------------- weight rounding
__global__ void round_copy(const float* __restrict__ in, float* __restrict__ out) {
    int i = blockIdx.x * blockDim.x + threadIdx.x;
    float4 v = ((const float4*)in)[i];
    v.x = tf32f(v.x); v.y = tf32f(v.y); v.z = tf32f(v.z); v.w = tf32f(v.w);
    ((float4*)out)[i] = v;
}

// ---------------------------------------------------------------- tf32 mma GEMM
// C[M,N] = A[M,K] * B  (+bias +residual, *scale)
//   BT=0: B is [K,N] row-major;  BT=1: B is [N,K] row-major (C = A * B^T)
// Inputs must already be tf32-representable.
template <int BT>
__global__ void __launch_bounds__(256, 2)
mma_gemm(const float* __restrict__ A, const float* __restrict__ B,
         float* __restrict__ C, int K, int lda, int ldb, int ldc,
         const float* __restrict__ bias, const float* __restrict__ residual,
         float scale, int causal_skip, int causal_klimit, int round_out,
         size_t sA, size_t sB, size_t sC, size_t sR) {
    if (causal_skip && blockIdx.x > blockIdx.y) return;

    __shared__ __align__(16) float As[2][BM * BMp];
    __shared__ __align__(16) float Bs[2][BT ? (BN * BMp) : (BK * BNp)];

    const int m0 = blockIdx.y * BM;
    const int n0 = blockIdx.x * BN;
    const int zb = blockIdx.z;
    A += sA * zb; B += sB * zb; C += sC * zb;
    if (residual) residual += sR * zb;

    const int kend = causal_klimit ? min(K, m0 + BM) : K;
    const int KT = kend / BK;

    const int tid  = threadIdx.x;
    const int lane = tid & 31;
    const int c = lane & 3;        // k-quad within fragment
    const int d = lane >> 2;       // row/col group within fragment
    const int wid = tid >> 5;
    const int wm = wid & 3;        // warp m index (0..3)
    const int wn = wid >> 2;       // warp n index (0..1)

    float acc[2][8][4];
    #pragma unroll
    for (int mt = 0; mt < 2; mt++)
        #pragma unroll
        for (int j = 0; j < 8; j++)
            #pragma unroll
            for (int t = 0; t < 4; t++) acc[mt][j][t] = 0.0f;

    float4 pa[2], pb[2];

    // global -> regs
    auto ldg = [&](int k0) {
        #pragma unroll
        for (int i = 0; i < 2; i++) {
            int idx = tid + i * 256;
            int r = idx >> 2, cq = idx & 3;
            pa[i] = *(const float4*)&A[(size_t)(m0 + r) * lda + k0 + cq * 4];
            if (BT) {
                pb[i] = *(const float4*)&B[(size_t)(n0 + r) * ldb + k0 + cq * 4];
            } else {
                int rb = idx >> 5, cb = idx & 31;
                pb[i] = *(const float4*)&B[(size_t)(k0 + rb) * ldb + n0 + cb * 4];
            }
        }
    };
    // regs -> smem (plain stores; inputs already tf32)
    auto sts = [&](int bf) {
        #pragma unroll
        for (int i = 0; i < 2; i++) {
            int idx = tid + i * 256;
            int r = idx >> 2, cq = idx & 3;
            *(float4*)&As[bf][r * BMp + cq * 4] = pa[i];
            if (BT) {
                *(float4*)&Bs[bf][r * BMp + cq * 4] = pb[i];
            } else {
                int rb = idx >> 5, cb = idx & 31;
                *(float4*)&Bs[bf][rb * BNp + cb * 4] = pb[i];
            }
        }
    };

    ldg(0);
    sts(0);
    __syncthreads();

    for (int kt = 0; kt < KT; kt++) {
        const int cur = kt & 1;
        if (kt + 1 < KT) ldg((kt + 1) * BK);

        #pragma unroll
        for (int s = 0; s < 2; s++) {
            const int kk = s * 8 + c;
            uint32_t a[2][4];
            #pragma unroll
            for (int mt = 0; mt < 2; mt++) {
                int r0 = wm * 32 + mt * 16 + d;
                a[mt][0] = __float_as_uint(As[cur][r0 * BMp + kk]);
                a[mt][1] = __float_as_uint(As[cur][(r0 + 8) * BMp + kk]);
                a[mt][2] = __float_as_uint(As[cur][r0 * BMp + kk + 4]);
                a[mt][3] = __float_as_uint(As[cur][(r0 + 8) * BMp + kk + 4]);
            }
            #pragma unroll
            for (int j = 0; j < 8; j++) {
                uint32_t b0, b1;
                if (BT) {
                    int rn = (wn * 64 + j * 8 + d) * BMp;
                    b0 = __float_as_uint(Bs[cur][rn + kk]);
                    b1 = __float_as_uint(Bs[cur][rn + kk + 4]);
                } else {
                    int nn = wn * 64 + j * 8 + d;
                    b0 = __float_as_uint(Bs[cur][kk * BNp + nn]);
                    b1 = __float_as_uint(Bs[cur][(kk + 4) * BNp + nn]);
                }
                mma8(acc[0][j], a[0], b0, b1);
                mma8(acc[1][j], a[1], b0, b1);
            }
        }

        // Single barrier per k-step: writing buffer cur^1 is safe because its
        // last readers were fenced by the barrier that ended iteration kt-1.
        if (kt + 1 < KT) {
            sts(cur ^ 1);
            __syncthreads();
        }
    }

    // ---- epilogue
    #pragma unroll
    for (int mt = 0; mt < 2; mt++) {
        int row0 = m0 + wm * 32 + mt * 16 + d;
        #pragma unroll
        for (int j = 0; j < 8; j++) {
            int col = n0 + wn * 64 + j * 8 + 2 * c;
            float bx = 0.0f, by = 0.0f;
            if (bias) { bx = bias[col]; by = bias[col + 1]; }
            {
                size_t o0 = (size_t)row0 * ldc + col;
                float2 vv;
                vv.x = acc[mt][j][0] * scale + bx;
                vv.y = acc[mt][j][1] * scale + by;
                if (residual) { vv.x += residual[o0]; vv.y += residual[o0 + 1]; }
                if (round_out) { vv.x = tf32f(vv.x); vv.y = tf32f(vv.y); }
                *(float2*)&C[o0] = vv;
            }
            {
                size_t o1 = (size_t)(row0 + 8) * ldc + col;
                float2 vv;
                vv.x = acc[mt][j][2] * scale + bx;
                vv.y = acc[mt][j][3] * scale + by;
                if (residual) { vv.x += residual[o1]; vv.y += residual[o1 + 1]; }
                if (round_out) { vv.x = tf32f(vv.x); vv.y = tf32f(vv.y); }
                *(float2*)&C[o1] = vv;
            }
        }
    }
}

// ---------------------------------------------------------------- softmax (tf32-rounded probs)
__global__ void softmax_causal_kernel() {
    int row = blockIdx.x;
    int s = row & (SEQ - 1);
    float* p = g_attn + (size_t)row * SEQ;
    int L = s + 1;
    __shared__ float red[256];
    int tid = threadIdx.x;

    float m = -1e30f;
    for (int t = tid; t < L; t += 256) m = fmaxf(m, p[t]);
    red[tid] = m; __syncthreads();
    #pragma unroll
    for (int o = 128; o > 0; o >>= 1) {
        if (tid < o) red[tid] = fmaxf(red[tid], red[tid + o]);
        __syncthreads();
    }
    m = red[0]; __syncthreads();

    float sum = 0.0f;
    for (int t = tid; t < L; t += 256) {
        float e = __expf(p[t] - m);
        p[t] = e;
        sum += e;
    }
    red[tid] = sum; __syncthreads();
    #pragma unroll
    for (int o = 128; o > 0; o >>= 1) {
        if (tid < o) red[tid] += red[tid + o];
        __syncthreads();
    }
    float inv = 1.0f / red[0];

    for (int t = tid; t < L; t += 256) p[t] = tf32f(p[t] * inv);
    for (int t = L + tid; t < SEQ; t += 256) p[t] = 0.0f;
}

// ---------------------------------------------------------------- launch
extern "C" void kernel_launch(void* const* d_in, const int* in_sizes, int n_in,
                              void* d_out, int out_size) {
    const int*   x    = (const int*)  d_in[0];
    const float* emb  = (const float*)d_in[1];
    const float* pos  = (const float*)d_in[2];
    const float* Wk   = (const float*)d_in[3];
    const float* Wq   = (const float*)d_in[4];
    const float* Wv   = (const float*)d_in[5];
    const float* Wo   = (const float*)d_in[6];
    const float* bo   = (const float*)d_in[7];
    float* out = (float*)d_out;

    static float *h = nullptr, *qkv, *attn, *z, *wR;
    if (!h) {
        cudaGetSymbolAddress((void**)&h,    g_h);
        cudaGetSymbolAddress((void**)&qkv,  g_qkv);
        cudaGetSymbolAddress((void**)&attn, g_attn);
        cudaGetSymbolAddress((void**)&z,    g_z);
        cudaGetSymbolAddress((void**)&wR,   g_wR);
    }
    const size_t SH = (size_t)SEQ * HID;
    const size_t RH = (size_t)ROWS * HID;
    const size_t SS = (size_t)SEQ * SEQ;
    const size_t HH = (size_t)HID * HID;

    float* WqR = wR;
    float* WkR = wR + HH;
    float* WvR = wR + 2 * HH;
    float* WoR = wR + 3 * HH;

    // 0. tf32-round weights (one cheap streaming pass)
    round_copy<<<HH / 1024, 256>>>(Wq, WqR);
    round_copy<<<HH / 1024, 256>>>(Wk, WkR);
    round_copy<<<HH / 1024, 256>>>(Wv, WvR);
    round_copy<<<((size_t)HID * VOCAB_N) / 1024, 256>>>(Wo, WoR);

    // 1. embedding (rounded h)
    embed_kernel<<<ROWS, 256>>>(x, emb, pos);

    // 2. QKV projections: [4096,1024] x [1024,1024]  (rounded outputs)
    {
        dim3 grid(HID / BN, ROWS / BM, 1);
        mma_gemm<0><<<grid, 256>>>(h, WqR, qkv, HID, HID, HID, HID,
            nullptr, nullptr, 1.0f, 0, 0, 1, 0, 0, 0, 0);
        mma_gemm<0><<<grid, 256>>>(h, WkR, qkv + RH, HID, HID, HID, HID,
            nullptr, nullptr, 1.0f, 0, 0, 1, 0, 0, 0, 0);
        mma_gemm<0><<<grid, 256>>>(h, WvR, qkv + 2 * RH, HID, HID, HID, HID,
            nullptr, nullptr, 1.0f, 0, 0, 1, 0, 0, 0, 0);
    }

    // 3. scores = q k^T / 32 (causal blocks only); rounded scores
    {
        dim3 grid(SEQ / BN, SEQ / BM, BATCH);
        mma_gemm<1><<<grid, 256>>>(qkv, qkv + RH, attn, HID, HID, HID, SEQ,
            nullptr, nullptr, 1.0f / 32.0f, 1, 0, 1, SH, SH, SS, 0);
    }

    // 4. causal softmax in place (rounded probs)
    softmax_causal_kernel<<<ROWS, 256>>>();

    // 5. z = attn @ v + h  (K causally limited; rounded z)
    {
        dim3 grid(HID / BN, SEQ / BM, BATCH);
        mma_gemm<0><<<grid, 256>>>(attn, qkv + 2 * RH, z, SEQ, SEQ, HID, HID,
            nullptr, h, 1.0f, 0, 1, 1, SS, SH, SH, SH);
    }

    // 6. out = z @ Wo + bo (NOT rounded)
    {
        dim3 grid(VOCAB_N / BN, ROWS / BM, 1);
        mma_gemm<0><<<grid, 256>>>(z, WoR, out, HID, HID, VOCAB_N, VOCAB_N,
            bo, nullptr, 1.0f, 0, 0, 0, 0, 0, 0, 0);
    }
}

// round 10
// speedup vs baseline: 5.5643x; 1.6958x over previous
#include <cuda_runtime.h>
#include <cuda_fp16.h>
#include <math.h>
#include <stdint.h>

// ---------------------------------------------------------------- constants
#define BATCH   2
#define SEQ     2048
#define HID     1024
#define VOCAB_N 32000
#define ROWS    (BATCH * SEQ)     // 4096

#define BM 128
#define BN 128
#define BK 32      // halves of K per stage (2 x k16 mma steps)
#define STRH 40    // smem row stride in halves; 20 half2-words -> (20d+c) hits all 32 banks
#define STR2 20    // stride in half2 units

// ---------------------------------------------------------------- scratch (fp16 pipeline)
__device__ __half g_h[ROWS * HID];
__device__ __half g_qkv[3 * (size_t)ROWS * HID];           // q | k | v
__device__ __half g_attn[(size_t)BATCH * SEQ * SEQ];
__device__ __half g_z[ROWS * HID];
__device__ __half g_vT[(size_t)BATCH * HID * SEQ];         // v^T per batch [HID,SEQ]
__device__ __half g_wT[3 * (size_t)HID * HID + (size_t)HID * VOCAB_N]; // W^T fp16 [N,K]

// ---------------------------------------------------------------- helpers
__device__ __forceinline__ void mma16(float* cc, const uint32_t* a,
                                      uint32_t b0, uint32_t b1) {
    asm volatile(
        "mma.sync.aligned.m16n8k16.row.col.f32.f16.f16.f32 "
        "{%0,%1,%2,%3}, {%4,%5,%6,%7}, {%8,%9}, {%0,%1,%2,%3};"
        : "+f"(cc[0]), "+f"(cc[1]), "+f"(cc[2]), "+f"(cc[3])
        : "r"(a[0]), "r"(a[1]), "r"(a[2]), "r"(a[3]), "r"(b0), "r"(b1));
}

// ---------------------------------------------------------------- embedding -> fp16 h
__global__ void embed_kernel(const int* __restrict__ x,
                             const float* __restrict__ emb,
                             const float* __restrict__ pos) {
    int row = blockIdx.x;
    int s = row & (SEQ - 1);
    int tok = x[row];
    const float4* e  = (const float4*)(emb + (size_t)tok * HID);
    const float4* pe = (const float4*)(pos + (size_t)s * HID);
    __half2* o = (__half2*)(g_h + (size_t)row * HID);
    int t = threadIdx.x;               // 256 threads x 4 floats
    float4 a = e[t], b = pe[t];
    o[2 * t]     = __floats2half2_rn(a.x + b.x, a.y + b.y);
    o[2 * t + 1] = __floats2half2_rn(a.z + b.z, a.w + b.w);
}

// ---------------------------------------------------------------- weight convert+transpose
// W [Kd, Nd] f32 row-major  ->  out [Nd, Kd] fp16 row-major (K-major operand)
__global__ void wT_kernel(const float* __restrict__ W, __half* __restrict__ out,
                          int Kd, int Nd) {
    __shared__ float t[32][33];
    int c0 = blockIdx.x * 32;   // N
    int r0 = blockIdx.y * 32;   // K
    int xx = threadIdx.x, yy = threadIdx.y;   // (32,8)
    #pragma unroll
    for (int i = 0; i < 32; i += 8)
        t[yy + i][xx] = W[(size_t)(r0 + yy + i) * Nd + c0 + xx];
    __syncthreads();
    #pragma unroll
    for (int i = 0; i < 32; i += 8)
        out[(size_t)(c0 + yy + i) * Kd + r0 + xx] = __float2half_rn(t[xx][yy + i]);
}

// fp16 transpose: in [R, C] -> out [C, R], batched via blockIdx.z
__global__ void hT_kernel(const __half* __restrict__ in, __half* __restrict__ out,
                          int R, int C, size_t sIn, size_t sOut) {
    __shared__ __half t[32][33];
    int zb = blockIdx.z;
    in += sIn * zb; out += sOut * zb;
    int c0 = blockIdx.x * 32, r0 = blockIdx.y * 32;
    int xx = threadIdx.x, yy = threadIdx.y;
    #pragma unroll
    for (int i = 0; i < 32; i += 8)
        t[yy + i][xx] = in[(size_t)(r0 + yy + i) * C + c0 + xx];
    __syncthreads();
    #pragma unroll
    for (int i = 0; i < 32; i += 8)
        out[(size_t)(c0 + yy + i) * R + r0 + xx] = t[xx][yy + i];
}

// ---------------------------------------------------------------- fp16 mma GEMM
// C[M,N] = A[M,K] * B^T   with A [M,K] fp16 row-major, B [N,K] fp16 K-major.
// OUTF16=1: C fp16 (rne). OUTF16=0: C f32 (+f32 bias).
// residual (fp16) added pre-round. scale applied first.
template <int OUTF16>
__global__ void __launch_bounds__(256, 2)
hgemm(const __half* __restrict__ A, const __half* __restrict__ B,
      void* __restrict__ Cv, int K, int lda, int ldb, int ldc,
      const float* __restrict__ bias, const __half* __restrict__ residual,
      float scale, int causal_skip, int causal_klimit,
      size_t sA, size_t sB, size_t sC, size_t sR) {
    if (causal_skip && blockIdx.x > blockIdx.y) return;

    __shared__ __align__(16) __half As[2][BM * STRH];   // 10 KB each
    __shared__ __align__(16) __half Bs[2][BN * STRH];

    const int m0 = blockIdx.y * BM;
    const int n0 = blockIdx.x * BN;
    const int zb = blockIdx.z;
    A += sA * zb; B += sB * zb;
    if (residual) residual += sR * zb;

    const int kend = causal_klimit ? min(K, m0 + BM) : K;
    const int KT = kend / BK;

    const int tid  = threadIdx.x;
    const int lane = tid & 31;
    const int c = lane & 3;
    const int d = lane >> 2;
    const int wid = tid >> 5;
    const int wm = wid & 3;        // warp m (0..3): rows wm*32 .. +31
    const int wn = wid >> 2;       // warp n (0..1): cols wn*64 .. +63

    float acc[2][8][4];
    #pragma unroll
    for (int mt = 0; mt < 2; mt++)
        #pragma unroll
        for (int j = 0; j < 8; j++)
            #pragma unroll
            for (int t = 0; t < 4; t++) acc[mt][j][t] = 0.0f;

    uint4 pa[2], pb[2];
    // A tile: 128 rows x 64B (4 x 16B chunks); 512 chunks over 256 thr = 2 each
    auto ldg = [&](int k0) {
        #pragma unroll
        for (int i = 0; i < 2; i++) {
            int idx = tid + i * 256;
            int r = idx >> 2, ch = idx & 3;
            pa[i] = *(const uint4*)&A[(size_t)(m0 + r) * lda + k0 + ch * 8];
            pb[i] = *(const uint4*)&B[(size_t)(n0 + r) * ldb + k0 + ch * 8];
        }
    };
    auto sts = [&](int bf) {
        #pragma unroll
        for (int i = 0; i < 2; i++) {
            int idx = tid + i * 256;
            int r = idx >> 2, ch = idx & 3;
            *(uint4*)&As[bf][r * STRH + ch * 8] = pa[i];
            *(uint4*)&Bs[bf][r * STRH + ch * 8] = pb[i];
        }
    };

    ldg(0);
    sts(0);
    __syncthreads();

    for (int kt = 0; kt < KT; kt++) {
        const int cur = kt & 1;
        if (kt + 1 < KT) ldg((kt + 1) * BK);

        const uint32_t* A2 = (const uint32_t*)As[cur];   // half2 view
        const uint32_t* B2 = (const uint32_t*)Bs[cur];

        #pragma unroll
        for (int s = 0; s < 2; s++) {
            const int kk = s * 8 + c;          // half2 index of k-pair
            uint32_t a[2][4];
            #pragma unroll
            for (int mt = 0; mt < 2; mt++) {
                int r0 = (wm * 32 + mt * 16 + d) * STR2;
                a[mt][0] = A2[r0 + kk];
                a[mt][1] = A2[r0 + 8 * STR2 + kk];
                a[mt][2] = A2[r0 + kk + 4];
                a[mt][3] = A2[r0 + 8 * STR2 + kk + 4];
            }
            #pragma unroll
            for (int j = 0; j < 8; j++) {
                int rn = (wn * 64 + j * 8 + d) * STR2;
                uint32_t b0 = B2[rn + kk];
                uint32_t b1 = B2[rn + kk + 4];
                mma16(acc[0][j], a[0], b0, b1);
                mma16(acc[1][j], a[1], b0, b1);
            }
        }

        if (kt + 1 < KT) {
            sts(cur ^ 1);       // safe: last readers fenced by barrier ending kt-1
            __syncthreads();
        }
    }

    // ---- epilogue
    #pragma unroll
    for (int mt = 0; mt < 2; mt++) {
        int row0 = m0 + wm * 32 + mt * 16 + d;
        #pragma unroll
        for (int j = 0; j < 8; j++) {
            int col = n0 + wn * 64 + j * 8 + 2 * c;
            float bx = 0.0f, by = 0.0f;
            if (bias) { bx = bias[col]; by = bias[col + 1]; }
            #pragma unroll
            for (int hrow = 0; hrow < 2; hrow++) {
                int rr = row0 + hrow * 8;
                size_t o = (size_t)rr * ldc + col;
                float vx = acc[mt][j][2 * hrow + 0] * scale + bx;
                float vy = acc[mt][j][2 * hrow + 1] * scale + by;
                if (residual) {
                    float2 rv = __half22float2(*(const __half2*)&residual[o]);
                    vx += rv.x; vy += rv.y;
                }
                if (OUTF16) {
                    *(__half2*)&((__half*)Cv + sC * zb)[o] = __floats2half2_rn(vx, vy);
                } else {
                    *(float2*)&((float*)Cv + sC * zb)[o] = make_float2(vx, vy);
                }
            }
        }
    }
}

// ---------------------------------------------------------------- softmax (fp16 in/out)
__global__ void softmax_causal_kernel() {
    int row = blockIdx.x;
    int s = row & (SEQ - 1);
    __half* p = g_attn + (size_t)row * SEQ;
    int L = s + 1;
    __shared__ float red[256];
    int tid = threadIdx.x;

    float m = -1e30f;
    for (int t = tid; t < L; t += 256) m = fmaxf(m, __half2float(p[t]));
    red[tid] = m; __syncthreads();
    #pragma unroll
    for (int o = 128; o > 0; o >>= 1) {
        if (tid < o) red[tid] = fmaxf(red[tid], red[tid + o]);
        __syncthreads();
    }
    m = red[0]; __syncthreads();

    float sum = 0.0f;
    for (int t = tid; t < L; t += 256) sum += __expf(__half2float(p[t]) - m);
    red[tid] = sum; __syncthreads();
    #pragma unroll
    for (int o = 128; o > 0; o >>= 1) {
        if (tid < o) red[tid] += red[tid + o];
        __syncthreads();
    }
    float inv = 1.0f / red[0];

    for (int t = tid; t < L; t += 256)
        p[t] = __float2half_rn(__expf(__half2float(p[t]) - m) * inv);
    for (int t = L + tid; t < SEQ; t += 256) p[t] = __float2half_rn(0.0f);
}

// ---------------------------------------------------------------- launch
extern "C" void kernel_launch(void* const* d_in, const int* in_sizes, int n_in,
                              void* d_out, int out_size) {
    const int*   x    = (const int*)  d_in[0];
    const float* emb  = (const float*)d_in[1];
    const float* pos  = (const float*)d_in[2];
    const float* Wk   = (const float*)d_in[3];
    const float* Wq   = (const float*)d_in[4];
    const float* Wv   = (const float*)d_in[5];
    const float* Wo   = (const float*)d_in[6];
    const float* bo   = (const float*)d_in[7];
    float* out = (float*)d_out;

    static __half *h = nullptr, *qkv, *attn, *z, *vT, *wT;
    if (!h) {
        cudaGetSymbolAddress((void**)&h,    g_h);
        cudaGetSymbolAddress((void**)&qkv,  g_qkv);
        cudaGetSymbolAddress((void**)&attn, g_attn);
        cudaGetSymbolAddress((void**)&z,    g_z);
        cudaGetSymbolAddress((void**)&vT,   g_vT);
        cudaGetSymbolAddress((void**)&wT,   g_wT);
    }
    const size_t SH = (size_t)SEQ * HID;
    const size_t RH = (size_t)ROWS * HID;
    const size_t SS = (size_t)SEQ * SEQ;
    const size_t HH = (size_t)HID * HID;

    __half* WqT = wT;
    __half* WkT = wT + HH;
    __half* WvT = wT + 2 * HH;
    __half* WoT = wT + 3 * HH;

    dim3 tb(32, 8);

    // 0. weights -> fp16, transposed to K-major [N,K]
    wT_kernel<<<dim3(HID / 32, HID / 32), tb>>>(Wq, WqT, HID, HID);
    wT_kernel<<<dim3(HID / 32, HID / 32), tb>>>(Wk, WkT, HID, HID);
    wT_kernel<<<dim3(HID / 32, HID / 32), tb>>>(Wv, WvT, HID, HID);
    wT_kernel<<<dim3(VOCAB_N / 32, HID / 32), tb>>>(Wo, WoT, HID, VOCAB_N);

    // 1. embedding -> fp16 h
    embed_kernel<<<ROWS, 256>>>(x, emb, pos);

    // 2. QKV projections (fp16 out)
    {
        dim3 grid(HID / BN, ROWS / BM, 1);
        hgemm<1><<<grid, 256>>>(h, WqT, qkv, HID, HID, HID, HID,
            nullptr, nullptr, 1.0f, 0, 0, 0, 0, 0, 0);
        hgemm<1><<<grid, 256>>>(h, WkT, qkv + RH, HID, HID, HID, HID,
            nullptr, nullptr, 1.0f, 0, 0, 0, 0, 0, 0);
        hgemm<1><<<grid, 256>>>(h, WvT, qkv + 2 * RH, HID, HID, HID, HID,
            nullptr, nullptr, 1.0f, 0, 0, 0, 0, 0, 0);
    }

    // 3. scores = q k^T / 32 (causal blocks only); k is already [SEQ,HID] K-major
    {
        dim3 grid(SEQ / BN, SEQ / BM, BATCH);
        hgemm<1><<<grid, 256>>>(qkv, qkv + RH, attn, HID, HID, HID, SEQ,
            nullptr, nullptr, 1.0f / 32.0f, 1, 0, SH, SH, SS, 0);
    }

    // 4. causal softmax in place
    softmax_causal_kernel<<<ROWS, 256>>>();

    // 5. v^T per batch: [SEQ,HID] -> [HID,SEQ]
    hT_kernel<<<dim3(HID / 32, SEQ / 32, BATCH), tb>>>(
        qkv + 2 * RH, vT, SEQ, HID, SH, SH);

    // 6. z = attn @ v + h  (K causally limited; fp16 out)
    {
        dim3 grid(HID / BN, SEQ / BM, BATCH);
        hgemm<1><<<grid, 256>>>(attn, vT, z, SEQ, SEQ, SEQ, HID,
            nullptr, h, 1.0f, 0, 1, SS, SH, SH, SH);
    }

    // 7. out = z @ Wo + bo (f32 out)
    {
        dim3 grid(VOCAB_N / BN, ROWS / BM, 1);
        hgemm<0><<<grid, 256>>>(z, WoT, out, HID, HID, HID, VOCAB_N,
            bo, nullptr, 1.0f, 0, 0, 0, 0, 0, 0);
    }
}

// round 11
// speedup vs baseline: 6.1046x; 1.0971x over previous
#include <cuda_runtime.h>
#include <cuda_fp16.h>
#include <math.h>
#include <stdint.h>

// ---------------------------------------------------------------- constants
#define BATCH   2
#define SEQ     2048
#define HID     1024
#define VOCAB_N 32000
#define ROWS    (BATCH * SEQ)     // 4096

#define BM 128
#define BN 128
#define BK 32      // halves of K per stage (2 x k16 mma steps)
#define STRH 40    // smem row stride in halves; 80B stride -> LDSM phases conflict-free
#define STR2 20

// ---------------------------------------------------------------- scratch (fp16 pipeline)
__device__ __half g_h[ROWS * HID];
__device__ __half g_qkv[3 * (size_t)ROWS * HID];           // q | k | v
__device__ __half g_attn[(size_t)BATCH * SEQ * SEQ];
__device__ __half g_z[ROWS * HID];
__device__ __half g_vT[(size_t)BATCH * HID * SEQ];         // v^T per batch [HID,SEQ]
__device__ __half g_wT[3 * (size_t)HID * HID + (size_t)HID * VOCAB_N]; // W^T fp16 [N,K]

// ---------------------------------------------------------------- helpers
__device__ __forceinline__ void mma16(float* cc, const uint32_t* a,
                                      uint32_t b0, uint32_t b1) {
    asm volatile(
        "mma.sync.aligned.m16n8k16.row.col.f32.f16.f16.f32 "
        "{%0,%1,%2,%3}, {%4,%5,%6,%7}, {%8,%9}, {%0,%1,%2,%3};"
        : "+f"(cc[0]), "+f"(cc[1]), "+f"(cc[2]), "+f"(cc[3])
        : "r"(a[0]), "r"(a[1]), "r"(a[2]), "r"(a[3]), "r"(b0), "r"(b1));
}
__device__ __forceinline__ void ldsm4(uint32_t* r, uint32_t addr) {
    asm volatile("ldmatrix.sync.aligned.m8n8.x4.shared.b16 {%0,%1,%2,%3}, [%4];"
                 : "=r"(r[0]), "=r"(r[1]), "=r"(r[2]), "=r"(r[3]) : "r"(addr));
}

// ---------------------------------------------------------------- embedding -> fp16 h
__global__ void embed_kernel(const int* __restrict__ x,
                             const float* __restrict__ emb,
                             const float* __restrict__ pos) {
    int row = blockIdx.x;
    int s = row & (SEQ - 1);
    int tok = x[row];
    const float4* e  = (const float4*)(emb + (size_t)tok * HID);
    const float4* pe = (const float4*)(pos + (size_t)s * HID);
    __half2* o = (__half2*)(g_h + (size_t)row * HID);
    int t = threadIdx.x;
    float4 a = e[t], b = pe[t];
    o[2 * t]     = __floats2half2_rn(a.x + b.x, a.y + b.y);
    o[2 * t + 1] = __floats2half2_rn(a.z + b.z, a.w + b.w);
}

// ---------------------------------------------------------------- weight convert+transpose
__global__ void wT_kernel(const float* __restrict__ W, __half* __restrict__ out,
                          int Kd, int Nd) {
    __shared__ float t[32][33];
    int c0 = blockIdx.x * 32;   // N
    int r0 = blockIdx.y * 32;   // K
    int xx = threadIdx.x, yy = threadIdx.y;   // (32,8)
    #pragma unroll
    for (int i = 0; i < 32; i += 8)
        t[yy + i][xx] = W[(size_t)(r0 + yy + i) * Nd + c0 + xx];
    __syncthreads();
    #pragma unroll
    for (int i = 0; i < 32; i += 8)
        out[(size_t)(c0 + yy + i) * Kd + r0 + xx] = __float2half_rn(t[xx][yy + i]);
}

// fp16 transpose: in [R, C] -> out [C, R], batched via blockIdx.z
__global__ void hT_kernel(const __half* __restrict__ in, __half* __restrict__ out,
                          int R, int C, size_t sIn, size_t sOut) {
    __shared__ __half t[32][33];
    int zb = blockIdx.z;
    in += sIn * zb; out += sOut * zb;
    int c0 = blockIdx.x * 32, r0 = blockIdx.y * 32;
    int xx = threadIdx.x, yy = threadIdx.y;
    #pragma unroll
    for (int i = 0; i < 32; i += 8)
        t[yy + i][xx] = in[(size_t)(r0 + yy + i) * C + c0 + xx];
    __syncthreads();
    #pragma unroll
    for (int i = 0; i < 32; i += 8)
        out[(size_t)(c0 + yy + i) * R + r0 + xx] = t[xx][yy + i];
}

// ---------------------------------------------------------------- fp16 mma GEMM (ldmatrix mainloop)
// C[M,N] = A[M,K] * B^T   with A [M,K] fp16 row-major, B [N,K] fp16 K-major.
template <int OUTF16>
__global__ void __launch_bounds__(256, 2)
hgemm(const __half* __restrict__ A, const __half* __restrict__ B,
      void* __restrict__ Cv, int K, int lda, int ldb, int ldc,
      const float* __restrict__ bias, const __half* __restrict__ residual,
      float scale, int causal_skip, int causal_klimit,
      size_t sA, size_t sB, size_t sC, size_t sR) {
    if (causal_skip && blockIdx.x > blockIdx.y) return;

    __shared__ __align__(16) __half As[2][BM * STRH];
    __shared__ __align__(16) __half Bs[2][BN * STRH];

    const int m0 = blockIdx.y * BM;
    const int n0 = blockIdx.x * BN;
    const int zb = blockIdx.z;
    A += sA * zb; B += sB * zb;
    if (residual) residual += sR * zb;

    const int kend = causal_klimit ? min(K, m0 + BM) : K;
    const int KT = kend / BK;

    const int tid  = threadIdx.x;
    const int lane = tid & 31;
    const int c = lane & 3;
    const int d = lane >> 2;
    const int wid = tid >> 5;
    const int wm = wid & 3;        // warp m (0..3)
    const int wn = wid >> 2;       // warp n (0..1)

    float acc[2][8][4];
    #pragma unroll
    for (int mt = 0; mt < 2; mt++)
        #pragma unroll
        for (int j = 0; j < 8; j++)
            #pragma unroll
            for (int t = 0; t < 4; t++) acc[mt][j][t] = 0.0f;

    // --- ldmatrix per-thread base offsets (bytes) ---
    const int lg = lane >> 3, lr = lane & 7;
    const uint32_t aSm = (uint32_t)__cvta_generic_to_shared(&As[0][0]);
    const uint32_t bSm = (uint32_t)__cvta_generic_to_shared(&Bs[0][0]);
    const uint32_t aBuf = BM * STRH * 2;   // bytes per A buffer
    const uint32_t bBuf = BN * STRH * 2;
    // A x4 mats: rows+0/k+0, rows+8/k+0, rows+0/k+8, rows+8/k+8
    uint32_t aOff[2];
    #pragma unroll
    for (int mt = 0; mt < 2; mt++)
        aOff[mt] = ((wm * 32 + mt * 16 + (lg & 1) * 8 + lr) * STRH + (lg >> 1) * 8) * 2;
    // B x4 mats (pair p covers n8-tiles 2p,2p+1): rows+0/k+0, rows+0/k+8, rows+8/k+0, rows+8/k+8
    uint32_t bOff[4];
    #pragma unroll
    for (int p = 0; p < 4; p++)
        bOff[p] = ((wn * 64 + p * 16 + (lg >> 1) * 8 + lr) * STRH + (lg & 1) * 8) * 2;

    uint4 pa[2], pb[2];
    auto ldg = [&](int k0) {
        #pragma unroll
        for (int i = 0; i < 2; i++) {
            int idx = tid + i * 256;
            int r = idx >> 2, ch = idx & 3;
            pa[i] = *(const uint4*)&A[(size_t)(m0 + r) * lda + k0 + ch * 8];
            pb[i] = *(const uint4*)&B[(size_t)(n0 + r) * ldb + k0 + ch * 8];
        }
    };
    auto sts = [&](int bf) {
        #pragma unroll
        for (int i = 0; i < 2; i++) {
            int idx = tid + i * 256;
            int r = idx >> 2, ch = idx & 3;
            *(uint4*)&As[bf][r * STRH + ch * 8] = pa[i];
            *(uint4*)&Bs[bf][r * STRH + ch * 8] = pb[i];
        }
    };

    ldg(0);
    sts(0);
    __syncthreads();

    for (int kt = 0; kt < KT; kt++) {
        const int cur = kt & 1;
        if (kt + 1 < KT) ldg((kt + 1) * BK);

        const uint32_t aC = aSm + cur * aBuf;
        const uint32_t bC = bSm + cur * bBuf;

        #pragma unroll
        for (int s = 0; s < 2; s++) {
            const uint32_t so = s * 32;      // 16 halves = 32 bytes
            uint32_t a[2][4];
            ldsm4(a[0], aC + aOff[0] + so);
            ldsm4(a[1], aC + aOff[1] + so);
            uint32_t bf[16];
            ldsm4(bf +  0, bC + bOff[0] + so);
            ldsm4(bf +  4, bC + bOff[1] + so);
            ldsm4(bf +  8, bC + bOff[2] + so);
            ldsm4(bf + 12, bC + bOff[3] + so);
            #pragma unroll
            for (int j = 0; j < 8; j++) {
                mma16(acc[0][j], a[0], bf[2 * j], bf[2 * j + 1]);
                mma16(acc[1][j], a[1], bf[2 * j], bf[2 * j + 1]);
            }
        }

        if (kt + 1 < KT) {
            sts(cur ^ 1);       // safe: last readers fenced by barrier ending kt-1
            __syncthreads();
        }
    }

    // ---- epilogue
    #pragma unroll
    for (int mt = 0; mt < 2; mt++) {
        int row0 = m0 + wm * 32 + mt * 16 + d;
        #pragma unroll
        for (int j = 0; j < 8; j++) {
            int col = n0 + wn * 64 + j * 8 + 2 * c;
            float bx = 0.0f, by = 0.0f;
            if (bias) { bx = bias[col]; by = bias[col + 1]; }
            #pragma unroll
            for (int hrow = 0; hrow < 2; hrow++) {
                int rr = row0 + hrow * 8;
                size_t o = (size_t)rr * ldc + col;
                float vx = acc[mt][j][2 * hrow + 0] * scale + bx;
                float vy = acc[mt][j][2 * hrow + 1] * scale + by;
                if (residual) {
                    float2 rv = __half22float2(*(const __half2*)&residual[o]);
                    vx += rv.x; vy += rv.y;
                }
                if (OUTF16) {
                    *(__half2*)&((__half*)Cv + sC * zb)[o] = __floats2half2_rn(vx, vy);
                } else {
                    *(float2*)&((float*)Cv + sC * zb)[o] = make_float2(vx, vy);
                }
            }
        }
    }
}

// ---------------------------------------------------------------- softmax (fp16 in/out)
__global__ void softmax_causal_kernel() {
    int row = blockIdx.x;
    int s = row & (SEQ - 1);
    __half* p = g_attn + (size_t)row * SEQ;
    int L = s + 1;
    __shared__ float red[256];
    int tid = threadIdx.x;

    float m = -1e30f;
    for (int t = tid; t < L; t += 256) m = fmaxf(m, __half2float(p[t]));
    red[tid] = m; __syncthreads();
    #pragma unroll
    for (int o = 128; o > 0; o >>= 1) {
        if (tid < o) red[tid] = fmaxf(red[tid], red[tid + o]);
        __syncthreads();
    }
    m = red[0]; __syncthreads();

    float sum = 0.0f;
    for (int t = tid; t < L; t += 256) sum += __expf(__half2float(p[t]) - m);
    red[tid] = sum; __syncthreads();
    #pragma unroll
    for (int o = 128; o > 0; o >>= 1) {
        if (tid < o) red[tid] += red[tid + o];
        __syncthreads();
    }
    float inv = 1.0f / red[0];

    for (int t = tid; t < L; t += 256)
        p[t] = __float2half_rn(__expf(__half2float(p[t]) - m) * inv);
    for (int t = L + tid; t < SEQ; t += 256) p[t] = __float2half_rn(0.0f);
}

// ---------------------------------------------------------------- launch
extern "C" void kernel_launch(void* const* d_in, const int* in_sizes, int n_in,
                              void* d_out, int out_size) {
    const int*   x    = (const int*)  d_in[0];
    const float* emb  = (const float*)d_in[1];
    const float* pos  = (const float*)d_in[2];
    const float* Wk   = (const float*)d_in[3];
    const float* Wq   = (const float*)d_in[4];
    const float* Wv   = (const float*)d_in[5];
    const float* Wo   = (const float*)d_in[6];
    const float* bo   = (const float*)d_in[7];
    float* out = (float*)d_out;

    static __half *h = nullptr, *qkv, *attn, *z, *vT, *wT;
    if (!h) {
        cudaGetSymbolAddress((void**)&h,    g_h);
        cudaGetSymbolAddress((void**)&qkv,  g_qkv);
        cudaGetSymbolAddress((void**)&attn, g_attn);
        cudaGetSymbolAddress((void**)&z,    g_z);
        cudaGetSymbolAddress((void**)&vT,   g_vT);
        cudaGetSymbolAddress((void**)&wT,   g_wT);
    }
    const size_t SH = (size_t)SEQ * HID;
    const size_t RH = (size_t)ROWS * HID;
    const size_t SS = (size_t)SEQ * SEQ;
    const size_t HH = (size_t)HID * HID;

    __half* WqT = wT;
    __half* WkT = wT + HH;
    __half* WvT = wT + 2 * HH;
    __half* WoT = wT + 3 * HH;

    dim3 tb(32, 8);

    // 0. weights -> fp16, transposed to K-major [N,K]
    wT_kernel<<<dim3(HID / 32, HID / 32), tb>>>(Wq, WqT, HID, HID);
    wT_kernel<<<dim3(HID / 32, HID / 32), tb>>>(Wk, WkT, HID, HID);
    wT_kernel<<<dim3(HID / 32, HID / 32), tb>>>(Wv, WvT, HID, HID);
    wT_kernel<<<dim3(VOCAB_N / 32, HID / 32), tb>>>(Wo, WoT, HID, VOCAB_N);

    // 1. embedding -> fp16 h
    embed_kernel<<<ROWS, 256>>>(x, emb, pos);

    // 2. QKV projections (fp16 out)
    {
        dim3 grid(HID / BN, ROWS / BM, 1);
        hgemm<1><<<grid, 256>>>(h, WqT, qkv, HID, HID, HID, HID,
            nullptr, nullptr, 1.0f, 0, 0, 0, 0, 0, 0);
        hgemm<1><<<grid, 256>>>(h, WkT, qkv + RH, HID, HID, HID, HID,
            nullptr, nullptr, 1.0f, 0, 0, 0, 0, 0, 0);
        hgemm<1><<<grid, 256>>>(h, WvT, qkv + 2 * RH, HID, HID, HID, HID,
            nullptr, nullptr, 1.0f, 0, 0, 0, 0, 0, 0);
    }

    // 3. scores = q k^T / 32 (causal blocks only)
    {
        dim3 grid(SEQ / BN, SEQ / BM, BATCH);
        hgemm<1><<<grid, 256>>>(qkv, qkv + RH, attn, HID, HID, HID, SEQ,
            nullptr, nullptr, 1.0f / 32.0f, 1, 0, SH, SH, SS, 0);
    }

    // 4. causal softmax in place
    softmax_causal_kernel<<<ROWS, 256>>>();

    // 5. v^T per batch: [SEQ,HID] -> [HID,SEQ]
    hT_kernel<<<dim3(HID / 32, SEQ / 32, BATCH), tb>>>(
        qkv + 2 * RH, vT, SEQ, HID, SH, SH);

    // 6. z = attn @ v + h  (K causally limited; fp16 out)
    {
        dim3 grid(HID / BN, SEQ / BM, BATCH);
        hgemm<1><<<grid, 256>>>(attn, vT, z, SEQ, SEQ, SEQ, HID,
            nullptr, h, 1.0f, 0, 1, SS, SH, SH, SH);
    }

    // 7. out = z @ Wo + bo (f32 out)
    {
        dim3 grid(VOCAB_N / BN, ROWS / BM, 1);
        hgemm<0><<<grid, 256>>>(z, WoT, out, HID, HID, HID, VOCAB_N,
            bo, nullptr, 1.0f, 0, 0, 0, 0, 0, 0);
    }
}

// round 12
// speedup vs baseline: 6.1270x; 1.0037x over previous
#include <cuda_runtime.h>
#include <cuda_fp16.h>
#include <math.h>
#include <stdint.h>

// ---------------------------------------------------------------- constants
#define BATCH   2
#define SEQ     2048
#define HID     1024
#define VOCAB_N 32000
#define ROWS    (BATCH * SEQ)     // 4096

#define BM 128
#define BN 128
#define BK 32      // halves of K per stage (2 x k16 mma steps)
#define STRH 40    // smem row stride in halves; 80B stride -> LDSM phases conflict-free
#define GROUP_M 8  // CTA swizzle: m-tiles grouped for L2 reuse of B

// ---------------------------------------------------------------- scratch (fp16 pipeline)
__device__ __half g_h[ROWS * HID];
__device__ __half g_qkv[3 * (size_t)ROWS * HID];           // q | k | v
__device__ __half g_attn[(size_t)BATCH * SEQ * SEQ];
__device__ __half g_z[ROWS * HID];
__device__ __half g_vT[(size_t)BATCH * HID * SEQ];         // v^T per batch [HID,SEQ]
__device__ __half g_wT[3 * (size_t)HID * HID + (size_t)HID * VOCAB_N]; // W^T fp16 [N,K]

// ---------------------------------------------------------------- helpers
__device__ __forceinline__ void mma16(float* cc, const uint32_t* a,
                                      uint32_t b0, uint32_t b1) {
    asm volatile(
        "mma.sync.aligned.m16n8k16.row.col.f32.f16.f16.f32 "
        "{%0,%1,%2,%3}, {%4,%5,%6,%7}, {%8,%9}, {%0,%1,%2,%3};"
        : "+f"(cc[0]), "+f"(cc[1]), "+f"(cc[2]), "+f"(cc[3])
        : "r"(a[0]), "r"(a[1]), "r"(a[2]), "r"(a[3]), "r"(b0), "r"(b1));
}
__device__ __forceinline__ void ldsm4(uint32_t* r, uint32_t addr) {
    asm volatile("ldmatrix.sync.aligned.m8n8.x4.shared.b16 {%0,%1,%2,%3}, [%4];"
                 : "=r"(r[0]), "=r"(r[1]), "=r"(r[2]), "=r"(r[3]) : "r"(addr));
}

// ---------------------------------------------------------------- embedding -> fp16 h
__global__ void embed_kernel(const int* __restrict__ x,
                             const float* __restrict__ emb,
                             const float* __restrict__ pos) {
    int row = blockIdx.x;
    int s = row & (SEQ - 1);
    int tok = x[row];
    const float4* e  = (const float4*)(emb + (size_t)tok * HID);
    const float4* pe = (const float4*)(pos + (size_t)s * HID);
    __half2* o = (__half2*)(g_h + (size_t)row * HID);
    int t = threadIdx.x;
    float4 a = e[t], b = pe[t];
    o[2 * t]     = __floats2half2_rn(a.x + b.x, a.y + b.y);
    o[2 * t + 1] = __floats2half2_rn(a.z + b.z, a.w + b.w);
}

// ---------------------------------------------------------------- weight convert+transpose
__global__ void wT_kernel(const float* __restrict__ W, __half* __restrict__ out,
                          int Kd, int Nd) {
    __shared__ float t[32][33];
    int c0 = blockIdx.x * 32;   // N
    int r0 = blockIdx.y * 32;   // K
    int xx = threadIdx.x, yy = threadIdx.y;   // (32,8)
    #pragma unroll
    for (int i = 0; i < 32; i += 8)
        t[yy + i][xx] = W[(size_t)(r0 + yy + i) * Nd + c0 + xx];
    __syncthreads();
    #pragma unroll
    for (int i = 0; i < 32; i += 8)
        out[(size_t)(c0 + yy + i) * Kd + r0 + xx] = __float2half_rn(t[xx][yy + i]);
}

// fp16 transpose: in [R, C] -> out [C, R], batched via blockIdx.z
__global__ void hT_kernel(const __half* __restrict__ in, __half* __restrict__ out,
                          int R, int C, size_t sIn, size_t sOut) {
    __shared__ __half t[32][33];
    int zb = blockIdx.z;
    in += sIn * zb; out += sOut * zb;
    int c0 = blockIdx.x * 32, r0 = blockIdx.y * 32;
    int xx = threadIdx.x, yy = threadIdx.y;
    #pragma unroll
    for (int i = 0; i < 32; i += 8)
        t[yy + i][xx] = in[(size_t)(r0 + yy + i) * C + c0 + xx];
    __syncthreads();
    #pragma unroll
    for (int i = 0; i < 32; i += 8)
        out[(size_t)(c0 + yy + i) * R + r0 + xx] = t[xx][yy + i];
}

// ---------------------------------------------------------------- fp16 mma GEMM (ldmatrix + swizzle)
// C[M,N] = A[M,K] * B^T   with A [M,K] fp16 row-major, B [N,K] fp16 K-major.
// CTA swizzle: m-fastest within groups of GROUP_M for L2 reuse of B.
template <int OUTF16>
__global__ void __launch_bounds__(256, 2)
hgemm(const __half* __restrict__ A, const __half* __restrict__ B,
      void* __restrict__ Cv, int K, int lda, int ldb, int ldc,
      const float* __restrict__ bias, const __half* __restrict__ residual,
      float scale, int causal_skip, int causal_klimit,
      size_t sA, size_t sB, size_t sC, size_t sR) {
    // --- CTA swizzle (gridDim.y must be divisible by GROUP_M) ---
    const int NT = gridDim.x;
    const int tile = blockIdx.y * NT + blockIdx.x;
    const int per = GROUP_M * NT;
    const int mi = (tile / per) * GROUP_M + (tile % per) % GROUP_M;
    const int ni = (tile % per) / GROUP_M;
    if (causal_skip && ni > mi) return;

    __shared__ __align__(16) __half As[2][BM * STRH];
    __shared__ __align__(16) __half Bs[2][BN * STRH];

    const int m0 = mi * BM;
    const int n0 = ni * BN;
    const int zb = blockIdx.z;
    A += sA * zb; B += sB * zb;
    if (residual) residual += sR * zb;

    const int kend = causal_klimit ? min(K, m0 + BM) : K;
    const int KT = kend / BK;

    const int tid  = threadIdx.x;
    const int lane = tid & 31;
    const int c = lane & 3;
    const int d = lane >> 2;
    const int wid = tid >> 5;
    const int wm = wid & 3;        // warp m (0..3)
    const int wn = wid >> 2;       // warp n (0..1)

    float acc[2][8][4];
    #pragma unroll
    for (int mt = 0; mt < 2; mt++)
        #pragma unroll
        for (int j = 0; j < 8; j++)
            #pragma unroll
            for (int t = 0; t < 4; t++) acc[mt][j][t] = 0.0f;

    // --- ldmatrix per-thread base offsets (bytes) ---
    const int lg = lane >> 3, lr = lane & 7;
    const uint32_t aSm = (uint32_t)__cvta_generic_to_shared(&As[0][0]);
    const uint32_t bSm = (uint32_t)__cvta_generic_to_shared(&Bs[0][0]);
    const uint32_t aBuf = BM * STRH * 2;
    const uint32_t bBuf = BN * STRH * 2;
    uint32_t aOff[2];
    #pragma unroll
    for (int mt = 0; mt < 2; mt++)
        aOff[mt] = ((wm * 32 + mt * 16 + (lg & 1) * 8 + lr) * STRH + (lg >> 1) * 8) * 2;
    uint32_t bOff[4];
    #pragma unroll
    for (int p = 0; p < 4; p++)
        bOff[p] = ((wn * 64 + p * 16 + (lg >> 1) * 8 + lr) * STRH + (lg & 1) * 8) * 2;

    uint4 pa[2], pb[2];
    auto ldg = [&](int k0) {
        #pragma unroll
        for (int i = 0; i < 2; i++) {
            int idx = tid + i * 256;
            int r = idx >> 2, ch = idx & 3;
            pa[i] = *(const uint4*)&A[(size_t)(m0 + r) * lda + k0 + ch * 8];
            pb[i] = *(const uint4*)&B[(size_t)(n0 + r) * ldb + k0 + ch * 8];
        }
    };
    auto sts = [&](int bf) {
        #pragma unroll
        for (int i = 0; i < 2; i++) {
            int idx = tid + i * 256;
            int r = idx >> 2, ch = idx & 3;
            *(uint4*)&As[bf][r * STRH + ch * 8] = pa[i];
            *(uint4*)&Bs[bf][r * STRH + ch * 8] = pb[i];
        }
    };

    ldg(0);
    sts(0);
    __syncthreads();
    if (1 < KT) ldg(BK);          // prefetch tile 1 (consumed after compute(0))

    for (int kt = 0; kt < KT; kt++) {
        const int cur = kt & 1;
        const uint32_t aC = aSm + cur * aBuf;
        const uint32_t bC = bSm + cur * bBuf;

        #pragma unroll
        for (int s = 0; s < 2; s++) {
            const uint32_t so = s * 32;      // 16 halves = 32 bytes
            uint32_t a[2][4];
            ldsm4(a[0], aC + aOff[0] + so);
            ldsm4(a[1], aC + aOff[1] + so);
            uint32_t bf[16];
            ldsm4(bf +  0, bC + bOff[0] + so);
            ldsm4(bf +  4, bC + bOff[1] + so);
            ldsm4(bf +  8, bC + bOff[2] + so);
            ldsm4(bf + 12, bC + bOff[3] + so);
            #pragma unroll
            for (int j = 0; j < 8; j++) {
                mma16(acc[0][j], a[0], bf[2 * j], bf[2 * j + 1]);
                mma16(acc[1][j], a[1], bf[2 * j], bf[2 * j + 1]);
            }
        }

        if (kt + 1 < KT) {
            sts(cur ^ 1);         // regs from ldg issued a full iteration ago
            __syncthreads();
            if (kt + 2 < KT) ldg((kt + 2) * BK);   // 2-deep prefetch
        }
    }

    // ---- epilogue
    #pragma unroll
    for (int mt = 0; mt < 2; mt++) {
        int row0 = m0 + wm * 32 + mt * 16 + d;
        #pragma unroll
        for (int j = 0; j < 8; j++) {
            int col = n0 + wn * 64 + j * 8 + 2 * c;
            float bx = 0.0f, by = 0.0f;
            if (bias) { bx = bias[col]; by = bias[col + 1]; }
            #pragma unroll
            for (int hrow = 0; hrow < 2; hrow++) {
                int rr = row0 + hrow * 8;
                size_t o = (size_t)rr * ldc + col;
                float vx = acc[mt][j][2 * hrow + 0] * scale + bx;
                float vy = acc[mt][j][2 * hrow + 1] * scale + by;
                if (residual) {
                    float2 rv = __half22float2(*(const __half2*)&residual[o]);
                    vx += rv.x; vy += rv.y;
                }
                if (OUTF16) {
                    *(__half2*)&((__half*)Cv + sC * zb)[o] = __floats2half2_rn(vx, vy);
                } else {
                    *(float2*)&((float*)Cv + sC * zb)[o] = make_float2(vx, vy);
                }
            }
        }
    }
}

// ---------------------------------------------------------------- softmax (fp16 in/out)
__global__ void softmax_causal_kernel() {
    int row = blockIdx.x;
    int s = row & (SEQ - 1);
    __half* p = g_attn + (size_t)row * SEQ;
    int L = s + 1;
    __shared__ float red[256];
    int tid = threadIdx.x;

    float m = -1e30f;
    for (int t = tid; t < L; t += 256) m = fmaxf(m, __half2float(p[t]));
    red[tid] = m; __syncthreads();
    #pragma unroll
    for (int o = 128; o > 0; o >>= 1) {
        if (tid < o) red[tid] = fmaxf(red[tid], red[tid + o]);
        __syncthreads();
    }
    m = red[0]; __syncthreads();

    float sum = 0.0f;
    for (int t = tid; t < L; t += 256) sum += __expf(__half2float(p[t]) - m);
    red[tid] = sum; __syncthreads();
    #pragma unroll
    for (int o = 128; o > 0; o >>= 1) {
        if (tid < o) red[tid] += red[tid + o];
        __syncthreads();
    }
    float inv = 1.0f / red[0];

    for (int t = tid; t < L; t += 256)
        p[t] = __float2half_rn(__expf(__half2float(p[t]) - m) * inv);
    for (int t = L + tid; t < SEQ; t += 256) p[t] = __float2half_rn(0.0f);
}

// ---------------------------------------------------------------- launch
extern "C" void kernel_launch(void* const* d_in, const int* in_sizes, int n_in,
                              void* d_out, int out_size) {
    const int*   x    = (const int*)  d_in[0];
    const float* emb  = (const float*)d_in[1];
    const float* pos  = (const float*)d_in[2];
    const float* Wk   = (const float*)d_in[3];
    const float* Wq   = (const float*)d_in[4];
    const float* Wv   = (const float*)d_in[5];
    const float* Wo   = (const float*)d_in[6];
    const float* bo   = (const float*)d_in[7];
    float* out = (float*)d_out;

    static __half *h = nullptr, *qkv, *attn, *z, *vT, *wT;
    if (!h) {
        cudaGetSymbolAddress((void**)&h,    g_h);
        cudaGetSymbolAddress((void**)&qkv,  g_qkv);
        cudaGetSymbolAddress((void**)&attn, g_attn);
        cudaGetSymbolAddress((void**)&z,    g_z);
        cudaGetSymbolAddress((void**)&vT,   g_vT);
        cudaGetSymbolAddress((void**)&wT,   g_wT);
    }
    const size_t SH = (size_t)SEQ * HID;
    const size_t RH = (size_t)ROWS * HID;
    const size_t SS = (size_t)SEQ * SEQ;
    const size_t HH = (size_t)HID * HID;

    __half* WqT = wT;
    __half* WkT = wT + HH;
    __half* WvT = wT + 2 * HH;
    __half* WoT = wT + 3 * HH;

    dim3 tb(32, 8);

    // 0. weights -> fp16, transposed to K-major [N,K]
    wT_kernel<<<dim3(HID / 32, HID / 32), tb>>>(Wq, WqT, HID, HID);
    wT_kernel<<<dim3(HID / 32, HID / 32), tb>>>(Wk, WkT, HID, HID);
    wT_kernel<<<dim3(HID / 32, HID / 32), tb>>>(Wv, WvT, HID, HID);
    wT_kernel<<<dim3(VOCAB_N / 32, HID / 32), tb>>>(Wo, WoT, HID, VOCAB_N);

    // 1. embedding -> fp16 h
    embed_kernel<<<ROWS, 256>>>(x, emb, pos);

    // 2. QKV projections (fp16 out)
    {
        dim3 grid(HID / BN, ROWS / BM, 1);
        hgemm<1><<<grid, 256>>>(h, WqT, qkv, HID, HID, HID, HID,
            nullptr, nullptr, 1.0f, 0, 0, 0, 0, 0, 0);
        hgemm<1><<<grid, 256>>>(h, WkT, qkv + RH, HID, HID, HID, HID,
            nullptr, nullptr, 1.0f, 0, 0, 0, 0, 0, 0);
        hgemm<1><<<grid, 256>>>(h, WvT, qkv + 2 * RH, HID, HID, HID, HID,
            nullptr, nullptr, 1.0f, 0, 0, 0, 0, 0, 0);
    }

    // 3. scores = q k^T / 32 (causal blocks only)
    {
        dim3 grid(SEQ / BN, SEQ / BM, BATCH);
        hgemm<1><<<grid, 256>>>(qkv, qkv + RH, attn, HID, HID, HID, SEQ,
            nullptr, nullptr, 1.0f / 32.0f, 1, 0, SH, SH, SS, 0);
    }

    // 4. causal softmax in place
    softmax_causal_kernel<<<ROWS, 256>>>();

    // 5. v^T per batch: [SEQ,HID] -> [HID,SEQ]
    hT_kernel<<<dim3(HID / 32, SEQ / 32, BATCH), tb>>>(
        qkv + 2 * RH, vT, SEQ, HID, SH, SH);

    // 6. z = attn @ v + h  (K causally limited; fp16 out)
    {
        dim3 grid(HID / BN, SEQ / BM, BATCH);
        hgemm<1><<<grid, 256>>>(attn, vT, z, SEQ, SEQ, SEQ, HID,
            nullptr, h, 1.0f, 0, 1, SS, SH, SH, SH);
    }

    // 7. out = z @ Wo + bo (f32 out)
    {
        dim3 grid(VOCAB_N / BN, ROWS / BM, 1);
        hgemm<0><<<grid, 256>>>(z, WoT, out, HID, HID, HID, VOCAB_N,
            bo, nullptr, 1.0f, 0, 0, 0, 0, 0, 0);
    }
}